// round 15
// baseline (speedup 1.0000x reference)
#include <cuda_runtime.h>
#include <cuda_fp16.h>
#include <mma.h>
#include <cstdint>

using namespace nvcuda;

// Problem constants
#define BB 2
#define NN 10000
#define MM 320000
#define DD 256
#define HH 8
#define ROWS (BB * NN)          // 20000 flattened GEMM rows
#define MPAD 20096              // 157 * 128 tiles
#define TOTAL_E (BB * MM)       // 640000 (b, edge) pairs
#define BK 32
#define LDA 40                  // As padded stride (halves): 80B, conflict-free LDSM
#define LDB 136                 // Bs padded stride (halves): 272B, conflict-free LDSM
#define LDS_STAGE 20            // epilogue staging stride (floats)
#define CAP 128                 // cached edges per bin (Poisson(32) max ~ 64)
#define SCAN_BLKS 40            // 40 * 256 = 10240 >= NN

// ---------------- scratch (device globals; no allocation allowed) ----------
__device__ __half g_qh[(size_t)MPAD * DD];      // fp16 q
__device__ __half g_kh[(size_t)MPAD * DD];      // fp16 k
__device__ int    g_mask32[2 * MM];             // canonical int32 mask
__device__ int    g_is64;                       // detected mask dtype
__device__ int    g_bin[NN + 1];                // bin start offsets (+ sentinel)
__device__ int    g_cursor[NN];                 // scatter cursors
__device__ int    g_scantmp[SCAN_BLKS * 256];   // local-exclusive scan temps
__device__ int    g_bsum[SCAN_BLKS];            // per-block sums
__device__ int    g_perm[MM];                   // edge ids sorted by i0
__device__ int    g_i1s[MM];                    // i1 sorted alongside perm

// ---------------- K_pre0: detect mask dtype + zero histogram ----------------
__global__ void detect_mask_kernel(const unsigned* __restrict__ mraw) {
    __shared__ int any_nonzero;
    if (threadIdx.x == 0) any_nonzero = 0;
    __syncthreads();
    unsigned v = mraw[threadIdx.x * 2 + 1];
    if (v != 0u) atomicOr(&any_nonzero, 1);
    for (int i = threadIdx.x; i <= NN; i += 256) g_bin[i] = 0;
    __syncthreads();
    if (threadIdx.x == 0) g_is64 = any_nonzero ? 0 : 1;
}

// ---------------- K_pre1: normalize mask (clamped) + histogram --------------
__global__ void convert_mask_kernel(const void* __restrict__ mraw) {
    int t = blockIdx.x * blockDim.x + threadIdx.x;
    if (t >= 2 * MM) return;
    long long v;
    if (g_is64) v = ((const long long*)mraw)[t];
    else        v = (long long)((const int*)mraw)[t];
    int vi = (int)v;
    vi = vi < 0 ? 0 : (vi >= NN ? NN - 1 : vi);
    g_mask32[t] = vi;
    if (t < MM) atomicAdd(&g_bin[vi], 1);       // fused histogram of i0
}

// ---------------- scan A: per-block 256-wide local exclusive scan -----------
__global__ void scanA_kernel() {
    __shared__ int sm[256];
    const int tid = threadIdx.x;
    const int idx = blockIdx.x * 256 + tid;
    const int c = (idx < NN) ? g_bin[idx] : 0;
    sm[tid] = c;
    __syncthreads();
    for (int s = 1; s < 256; s <<= 1) {
        int v = (tid >= s) ? sm[tid - s] : 0;
        __syncthreads();
        sm[tid] += v;
        __syncthreads();
    }
    g_scantmp[idx] = sm[tid] - c;
    if (tid == 255) g_bsum[blockIdx.x] = sm[255];
}

// ---------------- scan B: fold block sums, write final offsets --------------
__global__ void scanB_kernel() {
    __shared__ int bs[SCAN_BLKS];
    const int tid = threadIdx.x;
    if (tid < SCAN_BLKS) bs[tid] = g_bsum[tid];
    __syncthreads();
    int off = 0;
    for (int i = 0; i < blockIdx.x; i++) off += bs[i];
    const int idx = blockIdx.x * 256 + tid;
    if (idx <= NN) {
        const int fin = off + g_scantmp[idx];
        g_bin[idx] = fin;
        if (idx < NN) g_cursor[idx] = fin;
    }
}

// ---------------- scatter: edge ids + i1 into sorted order ------------------
__global__ void scatter_kernel() {
    int t = blockIdx.x * blockDim.x + threadIdx.x;
    if (t >= MM) return;
    int i0 = g_mask32[t];
    int i1 = g_mask32[MM + t];
    int pos = atomicAdd(&g_cursor[i0], 1);
    g_perm[pos] = t;
    g_i1s[pos]  = i1;
}

// ---------------- K1: HMMA GEMM; BOTH A and W read fp32, convert in-register
__global__ void __launch_bounds__(256, 2)
gemm_wmma_kernel(const float* __restrict__ xq, const float* __restrict__ xk,
                 const float* __restrict__ wq, const float* __restrict__ wk) {
    const int mat = blockIdx.z;
    const float* A = (mat == 0) ? xq : xk;
    const float* W = (mat == 0) ? wq : wk;
    __half*      C = (mat == 0) ? g_qh : g_kh;

    __shared__ __half As[2][128 * LDA];
    __shared__ __half Bs[2][BK * LDB];
    __shared__ float  stage[8][16 * LDS_STAGE];

    const int tid  = threadIdx.x;
    const int warp = tid >> 5;
    const int lane = tid & 31;
    const int wm = warp >> 1;
    const int wn = warp & 1;
    const int block_row = blockIdx.x * 128;
    const int block_col = blockIdx.y * 128;

    const int a_r0 = tid >> 2;
    const int a_r1 = a_r0 + 64;
    const int a_cf = (tid & 3) * 8;
    const int gr0 = min(block_row + a_r0, ROWS - 1);
    const int gr1 = min(block_row + a_r1, ROWS - 1);
    const float* a_src0 = A + (size_t)gr0 * DD + a_cf;
    const float* a_src1 = A + (size_t)gr1 * DD + a_cf;

    // B: 32x128 fp32 tile; thread covers 8 floats at rows b_r0 and b_r0+16
    const int b_r0 = tid >> 4;            // 0..15
    const int b_r1 = b_r0 + 16;           // 16..31
    const int b_c  = (tid & 15) * 8;      // 0..120
    const float* b_src0 = W + (size_t)b_r0 * DD + block_col + b_c;
    const float* b_src1 = W + (size_t)b_r1 * DD + block_col + b_c;

    wmma::fragment<wmma::accumulator, 16, 16, 16, float> acc[2][4];
    #pragma unroll
    for (int i = 0; i < 2; i++)
        #pragma unroll
        for (int j = 0; j < 4; j++) wmma::fill_fragment(acc[i][j], 0.0f);

    // helper lambda-free conversion macro pattern (compiler inlines)
    #define CVT8(dst, f0, f1) do {                                   \
        __half2 _h[4];                                               \
        _h[0] = __float22half2_rn(make_float2((f0).x, (f0).y));      \
        _h[1] = __float22half2_rn(make_float2((f0).z, (f0).w));      \
        _h[2] = __float22half2_rn(make_float2((f1).x, (f1).y));      \
        _h[3] = __float22half2_rn(make_float2((f1).z, (f1).w));      \
        *(uint4*)(dst) = *(uint4*)_h;                                \
    } while (0)

    {   // prologue: tile 0 -> stage 0
        float4 a00 = *(const float4*)(a_src0);
        float4 a01 = *(const float4*)(a_src0 + 4);
        float4 a10 = *(const float4*)(a_src1);
        float4 a11 = *(const float4*)(a_src1 + 4);
        float4 b00 = *(const float4*)(b_src0);
        float4 b01 = *(const float4*)(b_src0 + 4);
        float4 b10 = *(const float4*)(b_src1);
        float4 b11 = *(const float4*)(b_src1 + 4);
        CVT8(&As[0][a_r0 * LDA + a_cf], a00, a01);
        CVT8(&As[0][a_r1 * LDA + a_cf], a10, a11);
        CVT8(&Bs[0][b_r0 * LDB + b_c],  b00, b01);
        CVT8(&Bs[0][b_r1 * LDB + b_c],  b10, b11);
    }
    __syncthreads();

    int buf = 0;
    for (int k0 = 0; k0 < DD; k0 += BK) {
        const bool has_next = (k0 + BK < DD);
        float4 a00, a01, a10, a11, b00, b01, b10, b11;
        if (has_next) {                     // issue loads; consumed after mma
            a00 = *(const float4*)(a_src0 + k0 + BK);
            a01 = *(const float4*)(a_src0 + k0 + BK + 4);
            a10 = *(const float4*)(a_src1 + k0 + BK);
            a11 = *(const float4*)(a_src1 + k0 + BK + 4);
            b00 = *(const float4*)(b_src0 + (size_t)(k0 + BK) * DD);
            b01 = *(const float4*)(b_src0 + (size_t)(k0 + BK) * DD + 4);
            b10 = *(const float4*)(b_src1 + (size_t)(k0 + BK) * DD);
            b11 = *(const float4*)(b_src1 + (size_t)(k0 + BK) * DD + 4);
        }

        #pragma unroll
        for (int kk = 0; kk < BK; kk += 16) {
            wmma::fragment<wmma::matrix_a, 16, 16, 16, __half, wmma::row_major> af[2];
            wmma::fragment<wmma::matrix_b, 16, 16, 16, __half, wmma::row_major> bf[4];
            #pragma unroll
            for (int i = 0; i < 2; i++)
                wmma::load_matrix_sync(af[i], &As[buf][(wm * 32 + 16 * i) * LDA + kk], LDA);
            #pragma unroll
            for (int j = 0; j < 4; j++)
                wmma::load_matrix_sync(bf[j], &Bs[buf][kk * LDB + wn * 64 + 16 * j], LDB);
            #pragma unroll
            for (int i = 0; i < 2; i++)
                #pragma unroll
                for (int j = 0; j < 4; j++)
                    wmma::mma_sync(acc[i][j], af[i], bf[j], acc[i][j]);
        }

        if (has_next) {                     // stores after compute
            CVT8(&As[buf ^ 1][a_r0 * LDA + a_cf], a00, a01);
            CVT8(&As[buf ^ 1][a_r1 * LDA + a_cf], a10, a11);
            CVT8(&Bs[buf ^ 1][b_r0 * LDB + b_c],  b00, b01);
            CVT8(&Bs[buf ^ 1][b_r1 * LDB + b_c],  b10, b11);
        }
        __syncthreads();
        buf ^= 1;
    }

    #pragma unroll
    for (int i = 0; i < 2; i++) {
        #pragma unroll
        for (int j = 0; j < 4; j++) {
            wmma::store_matrix_sync(&stage[warp][0], acc[i][j], LDS_STAGE,
                                    wmma::mem_row_major);
            __syncwarp();
            const int r = lane >> 1, c = (lane & 1) * 8;
            const float* sp = &stage[warp][r * LDS_STAGE + c];
            __half2 h[4];
            #pragma unroll
            for (int x = 0; x < 4; x++)
                h[x] = __float22half2_rn(make_float2(sp[2 * x], sp[2 * x + 1]));
            __half* cp = C + (size_t)(block_row + wm * 32 + 16 * i + r) * DD
                       + block_col + wn * 64 + 16 * j + c;
            *(uint4*)cp = *(uint4*)h;
            __syncwarp();
        }
    }
    #undef CVT8
}

// ---------------- K2: FULLY FUSED per-bin edge kernel -----------------------
// One block per i0 bin. FOUR edges per warp-iteration: 8 independent k-row
// loads in flight (MLP=8). With avg cnt=32 and 8 warps, each warp's whole
// share issues in ONE load burst. seg in registers; e cached; normalize fused.
__device__ __forceinline__ float hdot8_h2(uint4 q, uint4 k) {
    const __half2* qh = (const __half2*)&q;
    const __half2* kh = (const __half2*)&k;
    __half2 acc = __hmul2(qh[0], kh[0]);
    acc = __hfma2(qh[1], kh[1], acc);
    acc = __hfma2(qh[2], kh[2], acc);
    acc = __hfma2(qh[3], kh[3], acc);
    return __low2float(acc) + __high2float(acc);
}

__global__ void __launch_bounds__(256)
edge_bin_kernel(float* __restrict__ out) {
    const int i0 = blockIdx.x;
    const int start = g_bin[i0];
    const int cnt   = g_bin[i0 + 1] - start;
    if (cnt == 0) return;

    __shared__ uint4 q_sm[2 * 32];          // q rows for b=0,1 (1 KB)
    __shared__ float seg_sm[16];            // seg[b][h]
    __shared__ int   i1_sm[CAP];            // staged i1 list
    __shared__ float e_sm[CAP * 2 * HH];    // cached e (8 KB)

    const int tid  = threadIdx.x;
    const int warp = tid >> 5;
    const int lane = tid & 31;

    if (tid < 64)
        q_sm[tid] = ((const uint4*)(g_qh + ((size_t)(tid >> 5) * NN + i0) * DD))[lane];
    if (tid < 16) seg_sm[tid] = 0.0f;
    {
        const int lim = cnt < CAP ? cnt : CAP;
        for (int i = tid; i < lim; i += 256) i1_sm[i] = g_i1s[start + i];
    }
    __syncthreads();

    // phase 1: FOUR edges per warp-iteration, both batches each (8 loads)
    float sa = 0.0f, sb = 0.0f;
    for (int e0 = warp; e0 < cnt; e0 += 32) {
        int ei[4];
        uint4 kv0[4], kv1[4];
        #pragma unroll
        for (int j = 0; j < 4; j++) {
            const int e = e0 + 8 * j;
            const int ec = (e < cnt) ? e : e0;      // clamp; discarded later
            ei[j] = e;
            const int i1 = (ec < CAP) ? i1_sm[ec] : g_i1s[start + ec];
            kv0[j] = ((const uint4*)(g_kh + (size_t)i1 * DD))[lane];
            kv1[j] = ((const uint4*)(g_kh + ((size_t)NN + i1) * DD))[lane];
        }

        #pragma unroll
        for (int j = 0; j < 4; j++) {
            if (ei[j] >= cnt) break;
            float p0 = hdot8_h2(q_sm[lane],      kv0[j]);
            float p1 = hdot8_h2(q_sm[32 + lane], kv1[j]);
            p0 += __shfl_down_sync(0xffffffffu, p0, 2, 4);
            p0 += __shfl_down_sync(0xffffffffu, p0, 1, 4);
            p1 += __shfl_down_sync(0xffffffffu, p1, 2, 4);
            p1 += __shfl_down_sync(0xffffffffu, p1, 1, 4);
            if ((lane & 3) == 0) {
                const int h = lane >> 2;
                const float v0 = __expf(p0 * 0.0625f);   // / sqrt(256)
                const float v1 = __expf(p1 * 0.0625f);
                if (ei[j] < CAP) {
                    e_sm[(2 * ei[j] + 0) * HH + h] = v0;
                    e_sm[(2 * ei[j] + 1) * HH + h] = v1;
                }
                sa += v0;
                sb += v1;
            }
        }
    }
    if ((lane & 3) == 0) {                  // one atomic burst per warp
        const int h = lane >> 2;
        atomicAdd(&seg_sm[h],      sa);
        atomicAdd(&seg_sm[HH + h], sb);
    }
    __syncthreads();

    const int ninst = cnt * 2;

    // phase 2a: normalize cached e, write out once (per-thread)
    const int lim = (ninst < 2 * CAP ? ninst : 2 * CAP) * HH;
    for (int idx = tid; idx < lim; idx += 256) {
        const int inst = idx >> 3, h = idx & 7;
        const int pos = start + (inst >> 1);
        const int b   = inst & 1;
        const int m   = g_perm[pos];
        out[((size_t)b * MM + m) * HH + h] = e_sm[idx] / (seg_sm[b * HH + h] + 1e-16f);
    }

    // phase 2b: overflow recompute (bins > CAP edges; ~never for Poisson(32))
    for (int e = CAP + warp; e < cnt; e += 8) {
        const int m  = g_perm[start + e];
        const int i1 = g_i1s[start + e];
        const uint4* k40 = (const uint4*)(g_kh + (size_t)i1 * DD);
        const uint4* k41 = (const uint4*)(g_kh + ((size_t)NN + i1) * DD);
        float p0 = hdot8_h2(q_sm[lane],      k40[lane]);
        float p1 = hdot8_h2(q_sm[32 + lane], k41[lane]);
        p0 += __shfl_down_sync(0xffffffffu, p0, 2, 4);
        p0 += __shfl_down_sync(0xffffffffu, p0, 1, 4);
        p1 += __shfl_down_sync(0xffffffffu, p1, 2, 4);
        p1 += __shfl_down_sync(0xffffffffu, p1, 1, 4);
        if ((lane & 3) == 0) {
            const int h = lane >> 2;
            out[((size_t)0 * MM + m) * HH + h] =
                __expf(p0 * 0.0625f) / (seg_sm[h] + 1e-16f);
            out[((size_t)1 * MM + m) * HH + h] =
                __expf(p1 * 0.0625f) / (seg_sm[HH + h] + 1e-16f);
        }
    }
}

// ---------------- launch: two concurrent pipelines --------------------------
// Pipeline A (default stream): GEMM (weights convert fused into B-load path)
// Pipeline B (side stream):    detect -> mask -> scan -> scatter
// Join before edge_bin. Fork/join via events (capture-safe pattern).
extern "C" void kernel_launch(void* const* d_in, const int* in_sizes, int n_in,
                              void* d_out, int out_size) {
    const float* x_q  = (const float*)d_in[0];
    const float* x_k  = (const float*)d_in[1];
    const void*  mask = (const void*)d_in[2];
    const float* w_q  = (const float*)d_in[3];
    const float* w_k  = (const float*)d_in[4];
    float* out = (float*)d_out;

    static cudaStream_t s_side = nullptr;
    static cudaEvent_t  ev_fork = nullptr, ev_join = nullptr;
    if (s_side == nullptr) {
        cudaStreamCreateWithFlags(&s_side, cudaStreamNonBlocking);
        cudaEventCreateWithFlags(&ev_fork, cudaEventDisableTiming);
        cudaEventCreateWithFlags(&ev_join, cudaEventDisableTiming);
    }

    // fork side stream off the main (capture) stream
    cudaEventRecord(ev_fork, 0);
    cudaStreamWaitEvent(s_side, ev_fork, 0);

    // pipeline B: mask -> histogram -> scan -> scatter (side stream)
    detect_mask_kernel<<<1, 256, 0, s_side>>>((const unsigned*)mask);
    convert_mask_kernel<<<(2 * MM + 255) / 256, 256, 0, s_side>>>(mask);
    scanA_kernel<<<SCAN_BLKS, 256, 0, s_side>>>();
    scanB_kernel<<<SCAN_BLKS, 256, 0, s_side>>>();
    scatter_kernel<<<(MM + 255) / 256, 256, 0, s_side>>>();
    cudaEventRecord(ev_join, s_side);

    // pipeline A: GEMM with fused fp32->fp16 conversion of A and W
    {
        dim3 grid(MPAD / 128, DD / 128, 2);
        gemm_wmma_kernel<<<grid, 256>>>(x_q, x_k, w_q, w_k);
    }

    // join, then the fused edge kernel
    cudaStreamWaitEvent(0, ev_join, 0);
    edge_bin_kernel<<<NN, 256>>>(out);
}

// round 16
// speedup vs baseline: 1.2030x; 1.2030x over previous
#include <cuda_runtime.h>
#include <cuda_fp16.h>
#include <mma.h>
#include <cstdint>

using namespace nvcuda;

// Problem constants
#define BB 2
#define NN 10000
#define MM 320000
#define DD 256
#define HH 8
#define ROWS (BB * NN)          // 20000 flattened GEMM rows
#define MPAD 20096              // 157 * 128 tiles
#define TOTAL_E (BB * MM)       // 640000 (b, edge) pairs
#define BK 32
#define LDA 40                  // As padded stride (halves): 80B, conflict-free LDSM
#define LDB 136                 // Bs padded stride (halves): 272B, conflict-free LDSM
#define LDS_STAGE 20            // epilogue staging stride (floats)
#define CAP 128                 // cached edges per bin (Poisson(32) max ~ 64)
#define SCAN_BLKS 40            // 40 * 256 = 10240 >= NN

// ---------------- scratch (device globals; no allocation allowed) ----------
__device__ __half g_wh[2 * DD * DD];            // fp16 w_q | w_k
__device__ __half g_qh[(size_t)MPAD * DD];      // fp16 q
__device__ __half g_kh[(size_t)MPAD * DD];      // fp16 k
__device__ int    g_mask32[2 * MM];             // canonical int32 mask
__device__ int    g_is64;                       // detected mask dtype
__device__ int    g_bin[NN + 1];                // bin start offsets (+ sentinel)
__device__ int    g_cursor[NN];                 // scatter cursors
__device__ int    g_scantmp[SCAN_BLKS * 256];   // local-exclusive scan temps
__device__ int    g_bsum[SCAN_BLKS];            // per-block sums
__device__ int    g_perm[MM];                   // edge ids sorted by i0
__device__ int    g_i1s[MM];                    // i1 sorted alongside perm

// ---------------- K_pre0: detect mask dtype + zero histogram ----------------
__global__ void detect_mask_kernel(const unsigned* __restrict__ mraw) {
    __shared__ int any_nonzero;
    if (threadIdx.x == 0) any_nonzero = 0;
    __syncthreads();
    unsigned v = mraw[threadIdx.x * 2 + 1];
    if (v != 0u) atomicOr(&any_nonzero, 1);
    for (int i = threadIdx.x; i <= NN; i += 256) g_bin[i] = 0;
    __syncthreads();
    if (threadIdx.x == 0) g_is64 = any_nonzero ? 0 : 1;
}

// ---------------- K_pre1: normalize mask (clamped) + histogram --------------
__global__ void convert_mask_kernel(const void* __restrict__ mraw) {
    int t = blockIdx.x * blockDim.x + threadIdx.x;
    if (t >= 2 * MM) return;
    long long v;
    if (g_is64) v = ((const long long*)mraw)[t];
    else        v = (long long)((const int*)mraw)[t];
    int vi = (int)v;
    vi = vi < 0 ? 0 : (vi >= NN ? NN - 1 : vi);
    g_mask32[t] = vi;
    if (t < MM) atomicAdd(&g_bin[vi], 1);       // fused histogram of i0
}

// ---------------- K_pre2: fp32 -> fp16 conversion of weights ----------------
__global__ void convert_weights_kernel(const float* __restrict__ wq,
                                       const float* __restrict__ wk) {
    const int t = blockIdx.x * blockDim.x + threadIdx.x;
    const int per_mat = DD * DD / 8;
    if (t >= 2 * per_mat) return;
    const int mat = t / per_mat;
    const int e   = (t % per_mat) * 8;
    const float* src = (mat == 0 ? wq : wk) + e;
    float4 f0 = *(const float4*)(src);
    float4 f1 = *(const float4*)(src + 4);
    __half2 h[4];
    h[0] = __float22half2_rn(make_float2(f0.x, f0.y));
    h[1] = __float22half2_rn(make_float2(f0.z, f0.w));
    h[2] = __float22half2_rn(make_float2(f1.x, f1.y));
    h[3] = __float22half2_rn(make_float2(f1.z, f1.w));
    *(uint4*)(g_wh + (size_t)mat * DD * DD + e) = *(uint4*)h;
}

// ---------------- scan A: per-block 256-wide local exclusive scan -----------
__global__ void scanA_kernel() {
    __shared__ int sm[256];
    const int tid = threadIdx.x;
    const int idx = blockIdx.x * 256 + tid;
    const int c = (idx < NN) ? g_bin[idx] : 0;
    sm[tid] = c;
    __syncthreads();
    for (int s = 1; s < 256; s <<= 1) {
        int v = (tid >= s) ? sm[tid - s] : 0;
        __syncthreads();
        sm[tid] += v;
        __syncthreads();
    }
    g_scantmp[idx] = sm[tid] - c;
    if (tid == 255) g_bsum[blockIdx.x] = sm[255];
}

// ---------------- scan B: fold block sums, write final offsets --------------
__global__ void scanB_kernel() {
    __shared__ int bs[SCAN_BLKS];
    const int tid = threadIdx.x;
    if (tid < SCAN_BLKS) bs[tid] = g_bsum[tid];
    __syncthreads();
    int off = 0;
    for (int i = 0; i < blockIdx.x; i++) off += bs[i];
    const int idx = blockIdx.x * 256 + tid;
    if (idx <= NN) {
        const int fin = off + g_scantmp[idx];
        g_bin[idx] = fin;
        if (idx < NN) g_cursor[idx] = fin;
    }
}

// ---------------- scatter: edge ids + i1 into sorted order ------------------
__global__ void scatter_kernel() {
    int t = blockIdx.x * blockDim.x + threadIdx.x;
    if (t >= MM) return;
    int i0 = g_mask32[t];
    int i1 = g_mask32[MM + t];
    int pos = atomicAdd(&g_cursor[i0], 1);
    g_perm[pos] = t;
    g_i1s[pos]  = i1;
}

// ---------------- K1: HMMA GEMM, double-buffered smem (R14 config) ----------
__global__ void __launch_bounds__(256, 2)
gemm_wmma_kernel(const float* __restrict__ xq, const float* __restrict__ xk) {
    const int mat = blockIdx.z;
    const float*  A = (mat == 0) ? xq : xk;
    const __half* B = g_wh + (size_t)mat * DD * DD;
    __half*       C = (mat == 0) ? g_qh : g_kh;

    __shared__ __half As[2][128 * LDA];
    __shared__ __half Bs[2][BK * LDB];
    __shared__ float  stage[8][16 * LDS_STAGE];

    const int tid  = threadIdx.x;
    const int warp = tid >> 5;
    const int lane = tid & 31;
    const int wm = warp >> 1;
    const int wn = warp & 1;
    const int block_row = blockIdx.x * 128;
    const int block_col = blockIdx.y * 128;

    const int a_r0 = tid >> 2;
    const int a_r1 = a_r0 + 64;
    const int a_cf = (tid & 3) * 8;
    const int gr0 = min(block_row + a_r0, ROWS - 1);
    const int gr1 = min(block_row + a_r1, ROWS - 1);
    const float* a_src0 = A + (size_t)gr0 * DD + a_cf;
    const float* a_src1 = A + (size_t)gr1 * DD + a_cf;

    const int b_r0 = tid >> 4,          b_c0 = (tid & 15) * 8;
    const int b_r1 = (tid + 256) >> 4,  b_c1 = ((tid + 256) & 15) * 8;
    const __half* b_src0 = B + (size_t)b_r0 * DD + block_col + b_c0;
    const __half* b_src1 = B + (size_t)b_r1 * DD + block_col + b_c1;

    wmma::fragment<wmma::accumulator, 16, 16, 16, float> acc[2][4];
    #pragma unroll
    for (int i = 0; i < 2; i++)
        #pragma unroll
        for (int j = 0; j < 4; j++) wmma::fill_fragment(acc[i][j], 0.0f);

    {
        float4 a00 = *(const float4*)(a_src0);
        float4 a01 = *(const float4*)(a_src0 + 4);
        float4 a10 = *(const float4*)(a_src1);
        float4 a11 = *(const float4*)(a_src1 + 4);
        uint4  bv0 = *(const uint4*)(b_src0);
        uint4  bv1 = *(const uint4*)(b_src1);
        __half2 h0[4], h1[4];
        h0[0] = __float22half2_rn(make_float2(a00.x, a00.y));
        h0[1] = __float22half2_rn(make_float2(a00.z, a00.w));
        h0[2] = __float22half2_rn(make_float2(a01.x, a01.y));
        h0[3] = __float22half2_rn(make_float2(a01.z, a01.w));
        h1[0] = __float22half2_rn(make_float2(a10.x, a10.y));
        h1[1] = __float22half2_rn(make_float2(a10.z, a10.w));
        h1[2] = __float22half2_rn(make_float2(a11.x, a11.y));
        h1[3] = __float22half2_rn(make_float2(a11.z, a11.w));
        *(uint4*)(&As[0][a_r0 * LDA + a_cf]) = *(uint4*)h0;
        *(uint4*)(&As[0][a_r1 * LDA + a_cf]) = *(uint4*)h1;
        *(uint4*)(&Bs[0][b_r0 * LDB + b_c0]) = bv0;
        *(uint4*)(&Bs[0][b_r1 * LDB + b_c1]) = bv1;
    }
    __syncthreads();

    int buf = 0;
    for (int k0 = 0; k0 < DD; k0 += BK) {
        const bool has_next = (k0 + BK < DD);
        float4 a00, a01, a10, a11;
        uint4  bv0, bv1;
        if (has_next) {
            a00 = *(const float4*)(a_src0 + k0 + BK);
            a01 = *(const float4*)(a_src0 + k0 + BK + 4);
            a10 = *(const float4*)(a_src1 + k0 + BK);
            a11 = *(const float4*)(a_src1 + k0 + BK + 4);
            bv0 = *(const uint4*)(b_src0 + (size_t)(k0 + BK) * DD);
            bv1 = *(const uint4*)(b_src1 + (size_t)(k0 + BK) * DD);
        }

        #pragma unroll
        for (int kk = 0; kk < BK; kk += 16) {
            wmma::fragment<wmma::matrix_a, 16, 16, 16, __half, wmma::row_major> af[2];
            wmma::fragment<wmma::matrix_b, 16, 16, 16, __half, wmma::row_major> bf[4];
            #pragma unroll
            for (int i = 0; i < 2; i++)
                wmma::load_matrix_sync(af[i], &As[buf][(wm * 32 + 16 * i) * LDA + kk], LDA);
            #pragma unroll
            for (int j = 0; j < 4; j++)
                wmma::load_matrix_sync(bf[j], &Bs[buf][kk * LDB + wn * 64 + 16 * j], LDB);
            #pragma unroll
            for (int i = 0; i < 2; i++)
                #pragma unroll
                for (int j = 0; j < 4; j++)
                    wmma::mma_sync(acc[i][j], af[i], bf[j], acc[i][j]);
        }

        if (has_next) {
            __half2 h0[4], h1[4];
            h0[0] = __float22half2_rn(make_float2(a00.x, a00.y));
            h0[1] = __float22half2_rn(make_float2(a00.z, a00.w));
            h0[2] = __float22half2_rn(make_float2(a01.x, a01.y));
            h0[3] = __float22half2_rn(make_float2(a01.z, a01.w));
            h1[0] = __float22half2_rn(make_float2(a10.x, a10.y));
            h1[1] = __float22half2_rn(make_float2(a10.z, a10.w));
            h1[2] = __float22half2_rn(make_float2(a11.x, a11.y));
            h1[3] = __float22half2_rn(make_float2(a11.z, a11.w));
            *(uint4*)(&As[buf ^ 1][a_r0 * LDA + a_cf]) = *(uint4*)h0;
            *(uint4*)(&As[buf ^ 1][a_r1 * LDA + a_cf]) = *(uint4*)h1;
            *(uint4*)(&Bs[buf ^ 1][b_r0 * LDB + b_c0]) = bv0;
            *(uint4*)(&Bs[buf ^ 1][b_r1 * LDB + b_c1]) = bv1;
        }
        __syncthreads();
        buf ^= 1;
    }

    #pragma unroll
    for (int i = 0; i < 2; i++) {
        #pragma unroll
        for (int j = 0; j < 4; j++) {
            wmma::store_matrix_sync(&stage[warp][0], acc[i][j], LDS_STAGE,
                                    wmma::mem_row_major);
            __syncwarp();
            const int r = lane >> 1, c = (lane & 1) * 8;
            const float* sp = &stage[warp][r * LDS_STAGE + c];
            __half2 h[4];
            #pragma unroll
            for (int x = 0; x < 4; x++)
                h[x] = __float22half2_rn(make_float2(sp[2 * x], sp[2 * x + 1]));
            __half* cp = C + (size_t)(block_row + wm * 32 + 16 * i + r) * DD
                       + block_col + wn * 64 + 16 * j + c;
            *(uint4*)cp = *(uint4*)h;
            __syncwarp();
        }
    }
}

// ---------------- K2: FULLY FUSED per-bin edge kernel (R14 + q hoisted) -----
// One block per i0 bin. TWO edges per warp-iteration (MLP=4, R14 config).
// NEW: q rows hoisted into registers once per thread -> removes 2 LDS.128
// per edge from the hot loop (smem crossbar pressure off the k-load path).
__device__ __forceinline__ float hdot8_h2(uint4 q, uint4 k) {
    const __half2* qh = (const __half2*)&q;
    const __half2* kh = (const __half2*)&k;
    __half2 acc = __hmul2(qh[0], kh[0]);
    acc = __hfma2(qh[1], kh[1], acc);
    acc = __hfma2(qh[2], kh[2], acc);
    acc = __hfma2(qh[3], kh[3], acc);
    return __low2float(acc) + __high2float(acc);
}

__global__ void __launch_bounds__(256)
edge_bin_kernel(float* __restrict__ out) {
    const int i0 = blockIdx.x;
    const int start = g_bin[i0];
    const int cnt   = g_bin[i0 + 1] - start;
    if (cnt == 0) return;

    __shared__ float seg_sm[16];            // seg[b][h]
    __shared__ int   i1_sm[CAP];            // staged i1 list
    __shared__ float e_sm[CAP * 2 * HH];    // cached e (8 KB)

    const int tid  = threadIdx.x;
    const int warp = tid >> 5;
    const int lane = tid & 31;

    if (tid < 16) seg_sm[tid] = 0.0f;
    {
        const int lim = cnt < CAP ? cnt : CAP;
        for (int i = tid; i < lim; i += 256) i1_sm[i] = g_i1s[start + i];
    }
    // q rows live in REGISTERS (loop-invariant; loaded once per thread)
    const uint4 qv0 = ((const uint4*)(g_qh + (size_t)i0 * DD))[lane];
    const uint4 qv1 = ((const uint4*)(g_qh + ((size_t)NN + i0) * DD))[lane];
    __syncthreads();

    // phase 1: TWO edges per warp-iteration, both batches each (4 loads)
    float sa = 0.0f, sb = 0.0f;
    for (int ea = warp; ea < cnt; ea += 16) {
        const int eb = ea + 8;
        const bool has2 = (eb < cnt);
        const int i1a = (ea < CAP) ? i1_sm[ea] : g_i1s[start + ea];
        const int i1b = has2 ? ((eb < CAP) ? i1_sm[eb] : g_i1s[start + eb]) : i1a;

        uint4 ka0 = ((const uint4*)(g_kh + (size_t)i1a * DD))[lane];
        uint4 ka1 = ((const uint4*)(g_kh + ((size_t)NN + i1a) * DD))[lane];
        uint4 kb0 = ((const uint4*)(g_kh + (size_t)i1b * DD))[lane];
        uint4 kb1 = ((const uint4*)(g_kh + ((size_t)NN + i1b) * DD))[lane];

        float pa0 = hdot8_h2(qv0, ka0);
        float pa1 = hdot8_h2(qv1, ka1);
        float pb0 = hdot8_h2(qv0, kb0);
        float pb1 = hdot8_h2(qv1, kb1);
        pa0 += __shfl_down_sync(0xffffffffu, pa0, 2, 4);
        pa0 += __shfl_down_sync(0xffffffffu, pa0, 1, 4);
        pa1 += __shfl_down_sync(0xffffffffu, pa1, 2, 4);
        pa1 += __shfl_down_sync(0xffffffffu, pa1, 1, 4);
        pb0 += __shfl_down_sync(0xffffffffu, pb0, 2, 4);
        pb0 += __shfl_down_sync(0xffffffffu, pb0, 1, 4);
        pb1 += __shfl_down_sync(0xffffffffu, pb1, 2, 4);
        pb1 += __shfl_down_sync(0xffffffffu, pb1, 1, 4);

        if ((lane & 3) == 0) {
            const int h = lane >> 2;
            const float ea0 = __expf(pa0 * 0.0625f);   // / sqrt(256)
            const float ea1 = __expf(pa1 * 0.0625f);
            if (ea < CAP) {
                e_sm[(2 * ea + 0) * HH + h] = ea0;
                e_sm[(2 * ea + 1) * HH + h] = ea1;
            }
            sa += ea0;
            sb += ea1;
            if (has2) {
                const float eb0 = __expf(pb0 * 0.0625f);
                const float eb1 = __expf(pb1 * 0.0625f);
                if (eb < CAP) {
                    e_sm[(2 * eb + 0) * HH + h] = eb0;
                    e_sm[(2 * eb + 1) * HH + h] = eb1;
                }
                sa += eb0;
                sb += eb1;
            }
        }
    }
    if ((lane & 3) == 0) {                  // one atomic burst per warp
        const int h = lane >> 2;
        atomicAdd(&seg_sm[h],      sa);
        atomicAdd(&seg_sm[HH + h], sb);
    }
    __syncthreads();

    const int ninst = cnt * 2;

    // phase 2a: normalize cached e, write out once (per-thread)
    const int lim = (ninst < 2 * CAP ? ninst : 2 * CAP) * HH;
    for (int idx = tid; idx < lim; idx += 256) {
        const int inst = idx >> 3, h = idx & 7;
        const int pos = start + (inst >> 1);
        const int b   = inst & 1;
        const int m   = g_perm[pos];
        out[((size_t)b * MM + m) * HH + h] = e_sm[idx] / (seg_sm[b * HH + h] + 1e-16f);
    }

    // phase 2b: overflow recompute (bins > CAP edges; ~never for Poisson(32))
    for (int e = CAP + warp; e < cnt; e += 8) {
        const int m  = g_perm[start + e];
        const int i1 = g_i1s[start + e];
        const uint4* k40 = (const uint4*)(g_kh + (size_t)i1 * DD);
        const uint4* k41 = (const uint4*)(g_kh + ((size_t)NN + i1) * DD);
        float p0 = hdot8_h2(qv0, k40[lane]);
        float p1 = hdot8_h2(qv1, k41[lane]);
        p0 += __shfl_down_sync(0xffffffffu, p0, 2, 4);
        p0 += __shfl_down_sync(0xffffffffu, p0, 1, 4);
        p1 += __shfl_down_sync(0xffffffffu, p1, 2, 4);
        p1 += __shfl_down_sync(0xffffffffu, p1, 1, 4);
        if ((lane & 3) == 0) {
            const int h = lane >> 2;
            out[((size_t)0 * MM + m) * HH + h] =
                __expf(p0 * 0.0625f) / (seg_sm[h] + 1e-16f);
            out[((size_t)1 * MM + m) * HH + h] =
                __expf(p1 * 0.0625f) / (seg_sm[HH + h] + 1e-16f);
        }
    }
}

// ---------------- launch: two concurrent pipelines --------------------------
extern "C" void kernel_launch(void* const* d_in, const int* in_sizes, int n_in,
                              void* d_out, int out_size) {
    const float* x_q  = (const float*)d_in[0];
    const float* x_k  = (const float*)d_in[1];
    const void*  mask = (const void*)d_in[2];
    const float* w_q  = (const float*)d_in[3];
    const float* w_k  = (const float*)d_in[4];
    float* out = (float*)d_out;

    static cudaStream_t s_side = nullptr;
    static cudaEvent_t  ev_fork = nullptr, ev_join = nullptr;
    if (s_side == nullptr) {
        cudaStreamCreateWithFlags(&s_side, cudaStreamNonBlocking);
        cudaEventCreateWithFlags(&ev_fork, cudaEventDisableTiming);
        cudaEventCreateWithFlags(&ev_join, cudaEventDisableTiming);
    }

    // fork side stream off the main (capture) stream
    cudaEventRecord(ev_fork, 0);
    cudaStreamWaitEvent(s_side, ev_fork, 0);

    // pipeline B: mask -> histogram -> scan -> scatter (side stream)
    detect_mask_kernel<<<1, 256, 0, s_side>>>((const unsigned*)mask);
    convert_mask_kernel<<<(2 * MM + 255) / 256, 256, 0, s_side>>>(mask);
    scanA_kernel<<<SCAN_BLKS, 256, 0, s_side>>>();
    scanB_kernel<<<SCAN_BLKS, 256, 0, s_side>>>();
    scatter_kernel<<<(MM + 255) / 256, 256, 0, s_side>>>();
    cudaEventRecord(ev_join, s_side);

    // pipeline A: weights -> GEMM (main stream)
    convert_weights_kernel<<<(2 * DD * DD / 8 + 255) / 256, 256>>>(w_q, w_k);
    {
        dim3 grid(MPAD / 128, DD / 128, 2);
        gemm_wmma_kernel<<<grid, 256>>>(x_q, x_k);
    }

    // join, then the fused edge kernel
    cudaStreamWaitEvent(0, ev_join, 0);
    edge_bin_kernel<<<NN, 256>>>(out);
}

// round 17
// speedup vs baseline: 1.3433x; 1.1166x over previous
#include <cuda_runtime.h>
#include <cuda_fp16.h>
#include <mma.h>
#include <cstdint>

using namespace nvcuda;

// Problem constants
#define BB 2
#define NN 10000
#define MM 320000
#define DD 256
#define HH 8
#define ROWS (BB * NN)          // 20000 flattened GEMM rows
#define MPAD 20096              // 157 * 128 tiles
#define TOTAL_E (BB * MM)       // 640000 (b, edge) pairs
#define BK 32
#define LDA 40                  // As padded stride (halves): 80B, conflict-free LDSM
#define LDB 136                 // Bs padded stride (halves): 272B, conflict-free LDSM
#define LDS_STAGE 20            // epilogue staging stride (floats)
#define CAP 128                 // cached edges per bin (Poisson(32) max ~ 64)
#define SCAN_BLKS 40            // 40 * 256 = 10240 >= NN
#define EB_THREADS 128          // edge_bin block size (4 warps)
#define EB_WARPS (EB_THREADS / 32)

// ---------------- scratch (device globals; no allocation allowed) ----------
__device__ __half g_wh[2 * DD * DD];            // fp16 w_q | w_k
__device__ __half g_qh[(size_t)MPAD * DD];      // fp16 q
__device__ __half g_kh[(size_t)MPAD * DD];      // fp16 k
__device__ int    g_mask32[2 * MM];             // canonical int32 mask
__device__ int    g_is64;                       // detected mask dtype
__device__ int    g_bin[NN + 1];                // bin start offsets (+ sentinel)
__device__ int    g_cursor[NN];                 // scatter cursors
__device__ int    g_scantmp[SCAN_BLKS * 256];   // local-exclusive scan temps
__device__ int    g_bsum[SCAN_BLKS];            // per-block sums
__device__ int    g_perm[MM];                   // edge ids sorted by i0
__device__ int    g_i1s[MM];                    // i1 sorted alongside perm

// ---------------- K_pre0: detect mask dtype + zero histogram ----------------
__global__ void detect_mask_kernel(const unsigned* __restrict__ mraw) {
    __shared__ int any_nonzero;
    if (threadIdx.x == 0) any_nonzero = 0;
    __syncthreads();
    unsigned v = mraw[threadIdx.x * 2 + 1];
    if (v != 0u) atomicOr(&any_nonzero, 1);
    for (int i = threadIdx.x; i <= NN; i += 256) g_bin[i] = 0;
    __syncthreads();
    if (threadIdx.x == 0) g_is64 = any_nonzero ? 0 : 1;
}

// ---------------- K_pre1: normalize mask (clamped) + histogram --------------
__global__ void convert_mask_kernel(const void* __restrict__ mraw) {
    int t = blockIdx.x * blockDim.x + threadIdx.x;
    if (t >= 2 * MM) return;
    long long v;
    if (g_is64) v = ((const long long*)mraw)[t];
    else        v = (long long)((const int*)mraw)[t];
    int vi = (int)v;
    vi = vi < 0 ? 0 : (vi >= NN ? NN - 1 : vi);
    g_mask32[t] = vi;
    if (t < MM) atomicAdd(&g_bin[vi], 1);       // fused histogram of i0
}

// ---------------- K_pre2: fp32 -> fp16 conversion of weights ----------------
__global__ void convert_weights_kernel(const float* __restrict__ wq,
                                       const float* __restrict__ wk) {
    const int t = blockIdx.x * blockDim.x + threadIdx.x;
    const int per_mat = DD * DD / 8;
    if (t >= 2 * per_mat) return;
    const int mat = t / per_mat;
    const int e   = (t % per_mat) * 8;
    const float* src = (mat == 0 ? wq : wk) + e;
    float4 f0 = *(const float4*)(src);
    float4 f1 = *(const float4*)(src + 4);
    __half2 h[4];
    h[0] = __float22half2_rn(make_float2(f0.x, f0.y));
    h[1] = __float22half2_rn(make_float2(f0.z, f0.w));
    h[2] = __float22half2_rn(make_float2(f1.x, f1.y));
    h[3] = __float22half2_rn(make_float2(f1.z, f1.w));
    *(uint4*)(g_wh + (size_t)mat * DD * DD + e) = *(uint4*)h;
}

// ---------------- scan A: per-block 256-wide local exclusive scan -----------
__global__ void scanA_kernel() {
    __shared__ int sm[256];
    const int tid = threadIdx.x;
    const int idx = blockIdx.x * 256 + tid;
    const int c = (idx < NN) ? g_bin[idx] : 0;
    sm[tid] = c;
    __syncthreads();
    for (int s = 1; s < 256; s <<= 1) {
        int v = (tid >= s) ? sm[tid - s] : 0;
        __syncthreads();
        sm[tid] += v;
        __syncthreads();
    }
    g_scantmp[idx] = sm[tid] - c;
    if (tid == 255) g_bsum[blockIdx.x] = sm[255];
}

// ---------------- scan B: fold block sums, write final offsets --------------
__global__ void scanB_kernel() {
    __shared__ int bs[SCAN_BLKS];
    const int tid = threadIdx.x;
    if (tid < SCAN_BLKS) bs[tid] = g_bsum[tid];
    __syncthreads();
    int off = 0;
    for (int i = 0; i < blockIdx.x; i++) off += bs[i];
    const int idx = blockIdx.x * 256 + tid;
    if (idx <= NN) {
        const int fin = off + g_scantmp[idx];
        g_bin[idx] = fin;
        if (idx < NN) g_cursor[idx] = fin;
    }
}

// ---------------- scatter: edge ids + i1 into sorted order ------------------
__global__ void scatter_kernel() {
    int t = blockIdx.x * blockDim.x + threadIdx.x;
    if (t >= MM) return;
    int i0 = g_mask32[t];
    int i1 = g_mask32[MM + t];
    int pos = atomicAdd(&g_cursor[i0], 1);
    g_perm[pos] = t;
    g_i1s[pos]  = i1;
}

// ---------------- K1: HMMA GEMM, double-buffered smem (R14 config) ----------
__global__ void __launch_bounds__(256, 2)
gemm_wmma_kernel(const float* __restrict__ xq, const float* __restrict__ xk) {
    const int mat = blockIdx.z;
    const float*  A = (mat == 0) ? xq : xk;
    const __half* B = g_wh + (size_t)mat * DD * DD;
    __half*       C = (mat == 0) ? g_qh : g_kh;

    __shared__ __half As[2][128 * LDA];
    __shared__ __half Bs[2][BK * LDB];
    __shared__ float  stage[8][16 * LDS_STAGE];

    const int tid  = threadIdx.x;
    const int warp = tid >> 5;
    const int lane = tid & 31;
    const int wm = warp >> 1;
    const int wn = warp & 1;
    const int block_row = blockIdx.x * 128;
    const int block_col = blockIdx.y * 128;

    const int a_r0 = tid >> 2;
    const int a_r1 = a_r0 + 64;
    const int a_cf = (tid & 3) * 8;
    const int gr0 = min(block_row + a_r0, ROWS - 1);
    const int gr1 = min(block_row + a_r1, ROWS - 1);
    const float* a_src0 = A + (size_t)gr0 * DD + a_cf;
    const float* a_src1 = A + (size_t)gr1 * DD + a_cf;

    const int b_r0 = tid >> 4,          b_c0 = (tid & 15) * 8;
    const int b_r1 = (tid + 256) >> 4,  b_c1 = ((tid + 256) & 15) * 8;
    const __half* b_src0 = B + (size_t)b_r0 * DD + block_col + b_c0;
    const __half* b_src1 = B + (size_t)b_r1 * DD + block_col + b_c1;

    wmma::fragment<wmma::accumulator, 16, 16, 16, float> acc[2][4];
    #pragma unroll
    for (int i = 0; i < 2; i++)
        #pragma unroll
        for (int j = 0; j < 4; j++) wmma::fill_fragment(acc[i][j], 0.0f);

    {
        float4 a00 = *(const float4*)(a_src0);
        float4 a01 = *(const float4*)(a_src0 + 4);
        float4 a10 = *(const float4*)(a_src1);
        float4 a11 = *(const float4*)(a_src1 + 4);
        uint4  bv0 = *(const uint4*)(b_src0);
        uint4  bv1 = *(const uint4*)(b_src1);
        __half2 h0[4], h1[4];
        h0[0] = __float22half2_rn(make_float2(a00.x, a00.y));
        h0[1] = __float22half2_rn(make_float2(a00.z, a00.w));
        h0[2] = __float22half2_rn(make_float2(a01.x, a01.y));
        h0[3] = __float22half2_rn(make_float2(a01.z, a01.w));
        h1[0] = __float22half2_rn(make_float2(a10.x, a10.y));
        h1[1] = __float22half2_rn(make_float2(a10.z, a10.w));
        h1[2] = __float22half2_rn(make_float2(a11.x, a11.y));
        h1[3] = __float22half2_rn(make_float2(a11.z, a11.w));
        *(uint4*)(&As[0][a_r0 * LDA + a_cf]) = *(uint4*)h0;
        *(uint4*)(&As[0][a_r1 * LDA + a_cf]) = *(uint4*)h1;
        *(uint4*)(&Bs[0][b_r0 * LDB + b_c0]) = bv0;
        *(uint4*)(&Bs[0][b_r1 * LDB + b_c1]) = bv1;
    }
    __syncthreads();

    int buf = 0;
    for (int k0 = 0; k0 < DD; k0 += BK) {
        const bool has_next = (k0 + BK < DD);
        float4 a00, a01, a10, a11;
        uint4  bv0, bv1;
        if (has_next) {
            a00 = *(const float4*)(a_src0 + k0 + BK);
            a01 = *(const float4*)(a_src0 + k0 + BK + 4);
            a10 = *(const float4*)(a_src1 + k0 + BK);
            a11 = *(const float4*)(a_src1 + k0 + BK + 4);
            bv0 = *(const uint4*)(b_src0 + (size_t)(k0 + BK) * DD);
            bv1 = *(const uint4*)(b_src1 + (size_t)(k0 + BK) * DD);
        }

        #pragma unroll
        for (int kk = 0; kk < BK; kk += 16) {
            wmma::fragment<wmma::matrix_a, 16, 16, 16, __half, wmma::row_major> af[2];
            wmma::fragment<wmma::matrix_b, 16, 16, 16, __half, wmma::row_major> bf[4];
            #pragma unroll
            for (int i = 0; i < 2; i++)
                wmma::load_matrix_sync(af[i], &As[buf][(wm * 32 + 16 * i) * LDA + kk], LDA);
            #pragma unroll
            for (int j = 0; j < 4; j++)
                wmma::load_matrix_sync(bf[j], &Bs[buf][kk * LDB + wn * 64 + 16 * j], LDB);
            #pragma unroll
            for (int i = 0; i < 2; i++)
                #pragma unroll
                for (int j = 0; j < 4; j++)
                    wmma::mma_sync(acc[i][j], af[i], bf[j], acc[i][j]);
        }

        if (has_next) {
            __half2 h0[4], h1[4];
            h0[0] = __float22half2_rn(make_float2(a00.x, a00.y));
            h0[1] = __float22half2_rn(make_float2(a00.z, a00.w));
            h0[2] = __float22half2_rn(make_float2(a01.x, a01.y));
            h0[3] = __float22half2_rn(make_float2(a01.z, a01.w));
            h1[0] = __float22half2_rn(make_float2(a10.x, a10.y));
            h1[1] = __float22half2_rn(make_float2(a10.z, a10.w));
            h1[2] = __float22half2_rn(make_float2(a11.x, a11.y));
            h1[3] = __float22half2_rn(make_float2(a11.z, a11.w));
            *(uint4*)(&As[buf ^ 1][a_r0 * LDA + a_cf]) = *(uint4*)h0;
            *(uint4*)(&As[buf ^ 1][a_r1 * LDA + a_cf]) = *(uint4*)h1;
            *(uint4*)(&Bs[buf ^ 1][b_r0 * LDB + b_c0]) = bv0;
            *(uint4*)(&Bs[buf ^ 1][b_r1 * LDB + b_c1]) = bv1;
        }
        __syncthreads();
        buf ^= 1;
    }

    #pragma unroll
    for (int i = 0; i < 2; i++) {
        #pragma unroll
        for (int j = 0; j < 4; j++) {
            wmma::store_matrix_sync(&stage[warp][0], acc[i][j], LDS_STAGE,
                                    wmma::mem_row_major);
            __syncwarp();
            const int r = lane >> 1, c = (lane & 1) * 8;
            const float* sp = &stage[warp][r * LDS_STAGE + c];
            __half2 h[4];
            #pragma unroll
            for (int x = 0; x < 4; x++)
                h[x] = __float22half2_rn(make_float2(sp[2 * x], sp[2 * x + 1]));
            __half* cp = C + (size_t)(block_row + wm * 32 + 16 * i + r) * DD
                       + block_col + wn * 64 + 16 * j + c;
            *(uint4*)cp = *(uint4*)h;
            __syncwarp();
        }
    }
}

// ---------------- K2: FULLY FUSED per-bin edge kernel (128 threads) ---------
// One 4-warp block per i0 bin: each warp owns ~8 edges (4 two-edge
// iterations) -> longer latency-amortizing loops, ~11 blocks/SM resident,
// half the barrier scope. q rows in registers; seg in registers + one
// atomic burst; e cached in smem; normalize fused.
__device__ __forceinline__ float hdot8_h2(uint4 q, uint4 k) {
    const __half2* qh = (const __half2*)&q;
    const __half2* kh = (const __half2*)&k;
    __half2 acc = __hmul2(qh[0], kh[0]);
    acc = __hfma2(qh[1], kh[1], acc);
    acc = __hfma2(qh[2], kh[2], acc);
    acc = __hfma2(qh[3], kh[3], acc);
    return __low2float(acc) + __high2float(acc);
}

__global__ void __launch_bounds__(EB_THREADS)
edge_bin_kernel(float* __restrict__ out) {
    const int i0 = blockIdx.x;
    const int start = g_bin[i0];
    const int cnt   = g_bin[i0 + 1] - start;
    if (cnt == 0) return;

    __shared__ float seg_sm[16];            // seg[b][h]
    __shared__ int   i1_sm[CAP];            // staged i1 list
    __shared__ float e_sm[CAP * 2 * HH];    // cached e (8 KB)

    const int tid  = threadIdx.x;
    const int warp = tid >> 5;
    const int lane = tid & 31;

    if (tid < 16) seg_sm[tid] = 0.0f;
    {
        const int lim = cnt < CAP ? cnt : CAP;
        for (int i = tid; i < lim; i += EB_THREADS) i1_sm[i] = g_i1s[start + i];
    }
    // q rows live in registers (loop-invariant; loaded once per thread)
    const uint4 qv0 = ((const uint4*)(g_qh + (size_t)i0 * DD))[lane];
    const uint4 qv1 = ((const uint4*)(g_qh + ((size_t)NN + i0) * DD))[lane];
    __syncthreads();

    // phase 1: TWO edges per warp-iteration, both batches each (4 loads)
    float sa = 0.0f, sb = 0.0f;
    for (int ea = warp; ea < cnt; ea += 2 * EB_WARPS) {
        const int eb = ea + EB_WARPS;
        const bool has2 = (eb < cnt);
        const int i1a = (ea < CAP) ? i1_sm[ea] : g_i1s[start + ea];
        const int i1b = has2 ? ((eb < CAP) ? i1_sm[eb] : g_i1s[start + eb]) : i1a;

        uint4 ka0 = ((const uint4*)(g_kh + (size_t)i1a * DD))[lane];
        uint4 ka1 = ((const uint4*)(g_kh + ((size_t)NN + i1a) * DD))[lane];
        uint4 kb0 = ((const uint4*)(g_kh + (size_t)i1b * DD))[lane];
        uint4 kb1 = ((const uint4*)(g_kh + ((size_t)NN + i1b) * DD))[lane];

        float pa0 = hdot8_h2(qv0, ka0);
        float pa1 = hdot8_h2(qv1, ka1);
        float pb0 = hdot8_h2(qv0, kb0);
        float pb1 = hdot8_h2(qv1, kb1);
        pa0 += __shfl_down_sync(0xffffffffu, pa0, 2, 4);
        pa0 += __shfl_down_sync(0xffffffffu, pa0, 1, 4);
        pa1 += __shfl_down_sync(0xffffffffu, pa1, 2, 4);
        pa1 += __shfl_down_sync(0xffffffffu, pa1, 1, 4);
        pb0 += __shfl_down_sync(0xffffffffu, pb0, 2, 4);
        pb0 += __shfl_down_sync(0xffffffffu, pb0, 1, 4);
        pb1 += __shfl_down_sync(0xffffffffu, pb1, 2, 4);
        pb1 += __shfl_down_sync(0xffffffffu, pb1, 1, 4);

        if ((lane & 3) == 0) {
            const int h = lane >> 2;
            const float ea0 = __expf(pa0 * 0.0625f);   // / sqrt(256)
            const float ea1 = __expf(pa1 * 0.0625f);
            if (ea < CAP) {
                e_sm[(2 * ea + 0) * HH + h] = ea0;
                e_sm[(2 * ea + 1) * HH + h] = ea1;
            }
            sa += ea0;
            sb += ea1;
            if (has2) {
                const float eb0 = __expf(pb0 * 0.0625f);
                const float eb1 = __expf(pb1 * 0.0625f);
                if (eb < CAP) {
                    e_sm[(2 * eb + 0) * HH + h] = eb0;
                    e_sm[(2 * eb + 1) * HH + h] = eb1;
                }
                sa += eb0;
                sb += eb1;
            }
        }
    }
    if ((lane & 3) == 0) {                  // one atomic burst per warp
        const int h = lane >> 2;
        atomicAdd(&seg_sm[h],      sa);
        atomicAdd(&seg_sm[HH + h], sb);
    }
    __syncthreads();

    const int ninst = cnt * 2;

    // phase 2a: normalize cached e, write out once (per-thread)
    const int lim = (ninst < 2 * CAP ? ninst : 2 * CAP) * HH;
    for (int idx = tid; idx < lim; idx += EB_THREADS) {
        const int inst = idx >> 3, h = idx & 7;
        const int pos = start + (inst >> 1);
        const int b   = inst & 1;
        const int m   = g_perm[pos];
        out[((size_t)b * MM + m) * HH + h] = e_sm[idx] / (seg_sm[b * HH + h] + 1e-16f);
    }

    // phase 2b: overflow recompute (bins > CAP edges; ~never for Poisson(32))
    for (int e = CAP + warp; e < cnt; e += EB_WARPS) {
        const int m  = g_perm[start + e];
        const int i1 = g_i1s[start + e];
        const uint4* k40 = (const uint4*)(g_kh + (size_t)i1 * DD);
        const uint4* k41 = (const uint4*)(g_kh + ((size_t)NN + i1) * DD);
        float p0 = hdot8_h2(qv0, k40[lane]);
        float p1 = hdot8_h2(qv1, k41[lane]);
        p0 += __shfl_down_sync(0xffffffffu, p0, 2, 4);
        p0 += __shfl_down_sync(0xffffffffu, p0, 1, 4);
        p1 += __shfl_down_sync(0xffffffffu, p1, 2, 4);
        p1 += __shfl_down_sync(0xffffffffu, p1, 1, 4);
        if ((lane & 3) == 0) {
            const int h = lane >> 2;
            out[((size_t)0 * MM + m) * HH + h] =
                __expf(p0 * 0.0625f) / (seg_sm[h] + 1e-16f);
            out[((size_t)1 * MM + m) * HH + h] =
                __expf(p1 * 0.0625f) / (seg_sm[HH + h] + 1e-16f);
        }
    }
}

// ---------------- launch: two concurrent pipelines --------------------------
extern "C" void kernel_launch(void* const* d_in, const int* in_sizes, int n_in,
                              void* d_out, int out_size) {
    const float* x_q  = (const float*)d_in[0];
    const float* x_k  = (const float*)d_in[1];
    const void*  mask = (const void*)d_in[2];
    const float* w_q  = (const float*)d_in[3];
    const float* w_k  = (const float*)d_in[4];
    float* out = (float*)d_out;

    static cudaStream_t s_side = nullptr;
    static cudaEvent_t  ev_fork = nullptr, ev_join = nullptr;
    if (s_side == nullptr) {
        cudaStreamCreateWithFlags(&s_side, cudaStreamNonBlocking);
        cudaEventCreateWithFlags(&ev_fork, cudaEventDisableTiming);
        cudaEventCreateWithFlags(&ev_join, cudaEventDisableTiming);
    }

    // fork side stream off the main (capture) stream
    cudaEventRecord(ev_fork, 0);
    cudaStreamWaitEvent(s_side, ev_fork, 0);

    // pipeline B: mask -> histogram -> scan -> scatter (side stream)
    detect_mask_kernel<<<1, 256, 0, s_side>>>((const unsigned*)mask);
    convert_mask_kernel<<<(2 * MM + 255) / 256, 256, 0, s_side>>>(mask);
    scanA_kernel<<<SCAN_BLKS, 256, 0, s_side>>>();
    scanB_kernel<<<SCAN_BLKS, 256, 0, s_side>>>();
    scatter_kernel<<<(MM + 255) / 256, 256, 0, s_side>>>();
    cudaEventRecord(ev_join, s_side);

    // pipeline A: weights -> GEMM (main stream)
    convert_weights_kernel<<<(2 * DD * DD / 8 + 255) / 256, 256>>>(w_q, w_k);
    {
        dim3 grid(MPAD / 128, DD / 128, 2);
        gemm_wmma_kernel<<<grid, 256>>>(x_q, x_k);
    }

    // join, then the fused edge kernel
    cudaStreamWaitEvent(0, ev_join, 0);
    edge_bin_kernel<<<NN, EB_THREADS>>>(out);
}